// round 10
// baseline (speedup 1.0000x reference)
#include <cuda_runtime.h>
#include <math.h>

#define H 768
#define H4 (H/4)
#define SLEN 512
#define BATCH 8
#define M_ROWS (BATCH*SLEN)        // 4096
#define NELEM (BATCH*SLEN*H)       // 3145728
#define NVEC (NELEM/4)             // 786432

#define ABLOCKS 1536               // 1536*256*2 == NVEC exactly
#define NTHREADS 256
#define TSTRIDE (ABLOCKS*NTHREADS) // 393216

// ---- device globals (scratch; no allocation allowed) ----
__device__ float g_scale[H];          // BN scale (conv path)
__device__ float g_shift[H];          // BN shift (conv path)
__device__ float g_y[NELEM];          // conv output scratch [b,s,o]
__device__ float g_y1[NELEM];         // depthwise output scratch [b,s,c]
__device__ unsigned int g_done = 0;   // conv-path arrival counter (self-resetting)

// =====================================================================
// Per-WARP gumbel straight-through gate: every warp computes it
// independently (lanes 0..9 active), no __syncthreads, result broadcast
// by shuffle. argmax(softmax(l)) == argmax(l); p_max = 1/sum exp(l-lmax).
// Off-index hardwts are exactly 0; selected is (1-p)+p.
// =====================================================================
__device__ __forceinline__ void gate_warp_all(const float* __restrict__ arch,
                                              const float* __restrict__ u,
                                              int& r_idx, float& r_w) {
    const unsigned FULL = 0xffffffffu;
    int lane = threadIdx.x & 31;
    bool act = (lane < 10);
    float a  = act ? __ldg(arch + lane) : -1e30f;
    float uu = act ? __ldg(u + lane) : 0.5f;
    // max over logits (16-lane butterfly; lanes 16-31 reduce garbage, unused)
    float m = a;
    #pragma unroll
    for (int o = 8; o > 0; o >>= 1) m = fmaxf(m, __shfl_xor_sync(FULL, m, o));
    // logsumexp
    float se = act ? expf(a - m) : 0.f;
    #pragma unroll
    for (int o = 8; o > 0; o >>= 1) se += __shfl_xor_sync(FULL, se, o);
    float lse = logf(se);
    // gumbel-perturbed logits / TEM(=10)
    float uc = fminf(fmaxf(uu, 1e-9f), 1.0f - 1e-9f);
    float g  = -logf(-logf(uc));
    float l  = act ? ((a - m - lse) + g) * 0.1f : -1e30f;
    // fused max+argmax (lowest index on tie, matching jnp.argmax)
    float bl = l; int bi = lane;
    #pragma unroll
    for (int o = 8; o > 0; o >>= 1) {
        float ol = __shfl_xor_sync(FULL, bl, o);
        int   oi = __shfl_xor_sync(FULL, bi, o);
        if (ol > bl || (ol == bl && oi < bi)) { bl = ol; bi = oi; }
    }
    // max prob = 1 / sum exp(l - l_max)
    float p = act ? expf(l - bl) : 0.f;
    #pragma unroll
    for (int o = 8; o > 0; o >>= 1) p += __shfl_xor_sync(FULL, p, o);
    // lanes 0..15 hold valid group-0 results; broadcast lane 0 to all 32
    float bp = 1.0f / p;
    float wv = (1.0f - bp) + bp;
    r_idx = __shfl_sync(FULL, bi, 0);
    r_w   = __shfl_sync(FULL, wv, 0);
}

// =====================================================================
// ONE kernel, ONE launch. Simple path: per-warp gate overlapped with
// 2 prefetched float4 per thread, then straight-line pool/skip/none.
// Conv path (never selected; correctness only): last block computes the
// whole branch alone with block-local syncs.
// =====================================================================
__global__ void __launch_bounds__(NTHREADS, 6)
fused_kernel(const float* __restrict__ x,
             const float* __restrict__ arch,
             const float* __restrict__ u,
             const float* __restrict__ wn3, const float* __restrict__ gn3, const float* __restrict__ bn3,
             const float* __restrict__ wn5, const float* __restrict__ gn5, const float* __restrict__ bn5,
             const float* __restrict__ wn7, const float* __restrict__ gn7, const float* __restrict__ bn7,
             const float* __restrict__ wd3, const float* __restrict__ wp3,
             const float* __restrict__ gd3, const float* __restrict__ bd3,
             const float* __restrict__ wd5, const float* __restrict__ wp5,
             const float* __restrict__ gd5, const float* __restrict__ bd5,
             const float* __restrict__ wd7, const float* __restrict__ wp7,
             const float* __restrict__ gd7, const float* __restrict__ bd7,
             float* __restrict__ out) {
    int tid = threadIdx.x;
    const float4* x4 = (const float4*)x;
    float4* o4 = (float4*)out;
    int v0 = blockIdx.x * NTHREADS + tid;
    int v1 = v0 + TSTRIDE;

    // Prefetch center elements BEFORE the gate (branch-independent).
    float4 xc0 = x4[v0];
    float4 xc1 = x4[v1];

    int idx; float w;
    gate_warp_all(arch, u, idx, w);

    // =========================== simple path ===========================
    if (idx < 3 || idx > 8) {
        if (idx == 0) {                          // none: out = x
            o4[v0] = xc0;
            o4[v1] = xc1;
        } else if (idx == 9) {                   // skip: out = (1+w)*x
            float wp1 = 1.0f + w;
            float4 r0, r1;
            r0.x = wp1 * xc0.x; r0.y = wp1 * xc0.y; r0.z = wp1 * xc0.z; r0.w = wp1 * xc0.w;
            r1.x = wp1 * xc1.x; r1.y = wp1 * xc1.y; r1.z = wp1 * xc1.z; r1.w = wp1 * xc1.w;
            o4[v0] = r0;
            o4[v1] = r1;
        } else {
            int s0 = (v0 / H4) % SLEN;
            int s1 = (v1 / H4) % SLEN;
            bool hm0 = (s0 > 0), hp0 = (s0 < SLEN - 1);
            bool hm1 = (s1 > 0), hp1 = (s1 < SLEN - 1);
            if (idx == 1) {                      // avg pool3 (pad counts as 0)
                float4 z = make_float4(0.f, 0.f, 0.f, 0.f);
                float4 xm0 = hm0 ? x4[v0 - H4] : z;
                float4 xp0 = hp0 ? x4[v0 + H4] : z;
                float4 xm1 = hm1 ? x4[v1 - H4] : z;
                float4 xp1 = hp1 ? x4[v1 + H4] : z;
                float w3 = w * (1.f / 3.f);
                float4 r0, r1;
                r0.x = w3 * (xm0.x + xc0.x + xp0.x) + xc0.x;
                r0.y = w3 * (xm0.y + xc0.y + xp0.y) + xc0.y;
                r0.z = w3 * (xm0.z + xc0.z + xp0.z) + xc0.z;
                r0.w = w3 * (xm0.w + xc0.w + xp0.w) + xc0.w;
                r1.x = w3 * (xm1.x + xc1.x + xp1.x) + xc1.x;
                r1.y = w3 * (xm1.y + xc1.y + xp1.y) + xc1.y;
                r1.z = w3 * (xm1.z + xc1.z + xp1.z) + xc1.z;
                r1.w = w3 * (xm1.w + xc1.w + xp1.w) + xc1.w;
                o4[v0] = r0;
                o4[v1] = r1;
            } else {                             // max pool3 (-inf pad)
                const float NINF = -__int_as_float(0x7f800000);
                float4 ni = make_float4(NINF, NINF, NINF, NINF);
                float4 xm0 = hm0 ? x4[v0 - H4] : ni;
                float4 xp0 = hp0 ? x4[v0 + H4] : ni;
                float4 xm1 = hm1 ? x4[v1 - H4] : ni;
                float4 xp1 = hp1 ? x4[v1 + H4] : ni;
                float4 r0, r1;
                r0.x = w * fmaxf(fmaxf(xm0.x, xc0.x), xp0.x) + xc0.x;
                r0.y = w * fmaxf(fmaxf(xm0.y, xc0.y), xp0.y) + xc0.y;
                r0.z = w * fmaxf(fmaxf(xm0.z, xc0.z), xp0.z) + xc0.z;
                r0.w = w * fmaxf(fmaxf(xm0.w, xc0.w), xp0.w) + xc0.w;
                r1.x = w * fmaxf(fmaxf(xm1.x, xc1.x), xp1.x) + xc1.x;
                r1.y = w * fmaxf(fmaxf(xm1.y, xc1.y), xp1.y) + xc1.y;
                r1.z = w * fmaxf(fmaxf(xm1.z, xc1.z), xp1.z) + xc1.z;
                r1.w = w * fmaxf(fmaxf(xm1.w, xc1.w), xp1.w) + xc1.w;
                o4[v0] = r0;
                o4[v1] = r1;
            }
        }
        return;
    }

    // ============================ conv path ============================
    // Last-arriving block does the whole branch alone (correctness only).
    __shared__ unsigned int s_last;
    if (tid == 0) {
        unsigned int prev = atomicAdd(&g_done, 1u);
        s_last = (prev == (unsigned)(ABLOCKS - 1)) ? 1u : 0u;
    }
    __syncthreads();
    if (!s_last) return;
    if (tid == 0) g_done = 0u;     // reset for next graph replay
    __syncthreads();

    bool is_nor = (idx <= 5);
    int k = is_nor ? (3 + 2 * (idx - 3)) : (3 + 2 * (idx - 6));

    if (is_nor) {
        // nor_conv: y[r,o] = sum_dk sum_i relu(x[r+dk-pad, i]) * W[o,i,dk]
        const float* W = (idx == 3) ? wn3 : ((idx == 4) ? wn5 : wn7);
        int pad = k >> 1;
        for (long e = tid; e < (long)M_ROWS * H; e += NTHREADS) {
            int o = (int)(e % H);
            int r = (int)(e / H);
            int b = r >> 9, s = r & 511;
            float acc = 0.f;
            for (int dk = 0; dk < k; dk++) {
                int s2 = s + dk - pad;
                if (s2 < 0 || s2 >= SLEN) continue;
                const float* xr = x + (long)((b << 9) + s2) * H;
                const float* wr = W + (long)o * H * k + dk;
                for (int i = 0; i < H; i++)
                    acc += fmaxf(xr[i], 0.f) * wr[(long)i * k];
            }
            g_y[e] = acc;
        }
    } else {
        // dil_conv: depthwise (dilation=2, pad=k-1) then pointwise
        const float* wd = (idx == 6) ? wd3 : ((idx == 7) ? wd5 : wd7);
        const float* wp = (idx == 6) ? wp3 : ((idx == 7) ? wp5 : wp7);
        for (long e = tid; e < (long)NELEM; e += NTHREADS) {
            int c = (int)(e % H);
            int r = (int)(e / H);
            int b = r >> 9, s = r & 511;
            float acc = 0.f;
            for (int dk = 0; dk < k; dk++) {
                int s2 = s + 2 * dk - (k - 1);
                if (s2 < 0 || s2 >= SLEN) continue;
                float xv = x[(long)((b << 9) + s2) * H + c];
                acc += wd[c * k + dk] * fmaxf(xv, 0.f);
            }
            g_y1[e] = acc;
        }
        __syncthreads();
        for (long e = tid; e < (long)M_ROWS * H; e += NTHREADS) {
            int o = (int)(e % H);
            int r = (int)(e / H);
            const float* yr = g_y1 + (long)r * H;
            const float* wr = wp + (long)o * H;
            float acc = 0.f;
            for (int i = 0; i < H; i++) acc += yr[i] * wr[i];
            g_y[e] = acc;
        }
    }
    __syncthreads();

    // BN stats (training mode) + normalize + residual
    {
        const float *ga, *be;
        switch (idx) {
            case 3: ga = gn3; be = bn3; break;
            case 4: ga = gn5; be = bn5; break;
            case 5: ga = gn7; be = bn7; break;
            case 6: ga = gd3; be = bd3; break;
            case 7: ga = gd5; be = bd5; break;
            default: ga = gd7; be = bd7; break;
        }
        const float invN = 1.f / (float)M_ROWS;
        for (int c = tid; c < H; c += NTHREADS) {
            float s = 0.f, q = 0.f;
            for (int r = 0; r < M_ROWS; r++) {
                float v = g_y[(long)r * H + c];
                s += v; q += v * v;
            }
            float mean = s * invN;
            float var  = q * invN - mean * mean;
            float inv  = rsqrtf(var + 1e-5f);
            float sc   = w * ga[c] * inv;
            g_scale[c] = sc;
            g_shift[c] = w * be[c] - mean * sc;
        }
        __syncthreads();
        for (long e = tid; e < (long)NELEM; e += NTHREADS) {
            int c = (int)(e % H);
            out[e] = g_scale[c] * g_y[e] + g_shift[c] + x[e];
        }
    }
}

// =====================================================================
extern "C" void kernel_launch(void* const* d_in, const int* in_sizes, int n_in,
                              void* d_out, int out_size) {
    const float* x     = (const float*)d_in[0];
    const float* u     = (const float*)d_in[1];
    const float* arch  = (const float*)d_in[2];
    fused_kernel<<<ABLOCKS, NTHREADS>>>(
        x, arch, u,
        (const float*)d_in[3],  (const float*)d_in[4],  (const float*)d_in[5],
        (const float*)d_in[6],  (const float*)d_in[7],  (const float*)d_in[8],
        (const float*)d_in[9],  (const float*)d_in[10], (const float*)d_in[11],
        (const float*)d_in[12], (const float*)d_in[13],
        (const float*)d_in[14], (const float*)d_in[15],
        (const float*)d_in[16], (const float*)d_in[17],
        (const float*)d_in[18], (const float*)d_in[19],
        (const float*)d_in[20], (const float*)d_in[21],
        (const float*)d_in[22], (const float*)d_in[23],
        (float*)d_out);
}

// round 11
// speedup vs baseline: 1.0295x; 1.0295x over previous
#include <cuda_runtime.h>
#include <math.h>

#define H 768
#define H4 (H/4)
#define SLEN 512
#define BATCH 8
#define M_ROWS (BATCH*SLEN)        // 4096
#define NELEM (BATCH*SLEN*H)       // 3145728
#define NVEC (NELEM/4)             // 786432

#define ABLOCKS 1536               // 1536*256*2 == NVEC exactly
#define NTHREADS 256
#define TSTRIDE (ABLOCKS*NTHREADS) // 393216

// ---- device globals (scratch; no allocation allowed) ----
__device__ float g_scale[H];          // BN scale (conv path)
__device__ float g_shift[H];          // BN shift (conv path)
__device__ float g_y[NELEM];          // conv output scratch [b,s,o]
__device__ float g_y1[NELEM];         // depthwise output scratch [b,s,c]
__device__ unsigned int g_done = 0;   // conv-path arrival counter (self-resetting)

// =====================================================================
// Minimal per-warp gumbel straight-through gate.
// KEY ALGEBRA: logits = (log_softmax(a)+g)/TEM = (a+g)/TEM - const, and
// softmax/argmax are shift-invariant => we never need max(a) or lse(a).
//   t_i = (a_i + g_i) * 0.1 ; idx = argmax t ; p_max = 1/sum exp(t - t_max)
// Off-index hardwts are exactly 0; selected entry is (1-p)+p.
// Uses MUFU intrinsics (__logf/__expf): ~1e-6 rel acc, bench tol 1e-3.
// =====================================================================
__device__ __forceinline__ void gate_warp_all(const float* __restrict__ arch,
                                              const float* __restrict__ u,
                                              int& r_idx, float& r_w) {
    const unsigned FULL = 0xffffffffu;
    int lane = threadIdx.x & 31;
    bool act = (lane < 10);
    float a  = act ? __ldg(arch + lane) : -1e30f;
    float uu = act ? __ldg(u + lane) : 0.5f;
    float uc = fminf(fmaxf(uu, 1e-9f), 1.0f - 1e-9f);
    float g  = -__logf(-__logf(uc));
    float t  = act ? (a + g) * 0.1f : -1e30f;
    // fused max+argmax (lowest index on tie, matching jnp.argmax)
    float bl = t; int bi = lane;
    #pragma unroll
    for (int o = 8; o > 0; o >>= 1) {
        float ol = __shfl_xor_sync(FULL, bl, o);
        int   oi = __shfl_xor_sync(FULL, bi, o);
        if (ol > bl || (ol == bl && oi < bi)) { bl = ol; bi = oi; }
    }
    // max prob = 1 / sum exp(t - t_max)
    float p = act ? __expf(t - bl) : 0.f;
    #pragma unroll
    for (int o = 8; o > 0; o >>= 1) p += __shfl_xor_sync(FULL, p, o);
    float bp = 1.0f / p;
    float wv = (1.0f - bp) + bp;
    r_idx = __shfl_sync(FULL, bi, 0);
    r_w   = __shfl_sync(FULL, wv, 0);
}

// =====================================================================
// ONE kernel, ONE launch. Simple path: per-warp mini-gate overlapped
// with 2 prefetched float4 per thread, then straight-line pool/skip/none.
// Conv path (never selected; correctness only): last block computes the
// whole branch alone with block-local syncs.
// =====================================================================
__global__ void __launch_bounds__(NTHREADS, 6)
fused_kernel(const float* __restrict__ x,
             const float* __restrict__ arch,
             const float* __restrict__ u,
             const float* __restrict__ wn3, const float* __restrict__ gn3, const float* __restrict__ bn3,
             const float* __restrict__ wn5, const float* __restrict__ gn5, const float* __restrict__ bn5,
             const float* __restrict__ wn7, const float* __restrict__ gn7, const float* __restrict__ bn7,
             const float* __restrict__ wd3, const float* __restrict__ wp3,
             const float* __restrict__ gd3, const float* __restrict__ bd3,
             const float* __restrict__ wd5, const float* __restrict__ wp5,
             const float* __restrict__ gd5, const float* __restrict__ bd5,
             const float* __restrict__ wd7, const float* __restrict__ wp7,
             const float* __restrict__ gd7, const float* __restrict__ bd7,
             float* __restrict__ out) {
    int tid = threadIdx.x;
    const float4* x4 = (const float4*)x;
    float4* o4 = (float4*)out;
    int v0 = blockIdx.x * NTHREADS + tid;
    int v1 = v0 + TSTRIDE;

    // Prefetch center elements BEFORE the gate (branch-independent).
    float4 xc0 = x4[v0];
    float4 xc1 = x4[v1];

    int idx; float w;
    gate_warp_all(arch, u, idx, w);

    // =========================== simple path ===========================
    if (idx < 3 || idx > 8) {
        if (idx == 0) {                          // none: out = x
            o4[v0] = xc0;
            o4[v1] = xc1;
        } else if (idx == 9) {                   // skip: out = (1+w)*x
            float wp1 = 1.0f + w;
            float4 r0, r1;
            r0.x = wp1 * xc0.x; r0.y = wp1 * xc0.y; r0.z = wp1 * xc0.z; r0.w = wp1 * xc0.w;
            r1.x = wp1 * xc1.x; r1.y = wp1 * xc1.y; r1.z = wp1 * xc1.z; r1.w = wp1 * xc1.w;
            o4[v0] = r0;
            o4[v1] = r1;
        } else {
            int s0 = (v0 / H4) % SLEN;
            int s1 = (v1 / H4) % SLEN;
            bool hm0 = (s0 > 0), hp0 = (s0 < SLEN - 1);
            bool hm1 = (s1 > 0), hp1 = (s1 < SLEN - 1);
            if (idx == 1) {                      // avg pool3 (pad counts as 0)
                float4 z = make_float4(0.f, 0.f, 0.f, 0.f);
                float4 xm0 = hm0 ? x4[v0 - H4] : z;
                float4 xp0 = hp0 ? x4[v0 + H4] : z;
                float4 xm1 = hm1 ? x4[v1 - H4] : z;
                float4 xp1 = hp1 ? x4[v1 + H4] : z;
                float w3 = w * (1.f / 3.f);
                float4 r0, r1;
                r0.x = w3 * (xm0.x + xc0.x + xp0.x) + xc0.x;
                r0.y = w3 * (xm0.y + xc0.y + xp0.y) + xc0.y;
                r0.z = w3 * (xm0.z + xc0.z + xp0.z) + xc0.z;
                r0.w = w3 * (xm0.w + xc0.w + xp0.w) + xc0.w;
                r1.x = w3 * (xm1.x + xc1.x + xp1.x) + xc1.x;
                r1.y = w3 * (xm1.y + xc1.y + xp1.y) + xc1.y;
                r1.z = w3 * (xm1.z + xc1.z + xp1.z) + xc1.z;
                r1.w = w3 * (xm1.w + xc1.w + xp1.w) + xc1.w;
                o4[v0] = r0;
                o4[v1] = r1;
            } else {                             // max pool3 (-inf pad)
                const float NINF = -__int_as_float(0x7f800000);
                float4 ni = make_float4(NINF, NINF, NINF, NINF);
                float4 xm0 = hm0 ? x4[v0 - H4] : ni;
                float4 xp0 = hp0 ? x4[v0 + H4] : ni;
                float4 xm1 = hm1 ? x4[v1 - H4] : ni;
                float4 xp1 = hp1 ? x4[v1 + H4] : ni;
                float4 r0, r1;
                r0.x = w * fmaxf(fmaxf(xm0.x, xc0.x), xp0.x) + xc0.x;
                r0.y = w * fmaxf(fmaxf(xm0.y, xc0.y), xp0.y) + xc0.y;
                r0.z = w * fmaxf(fmaxf(xm0.z, xc0.z), xp0.z) + xc0.z;
                r0.w = w * fmaxf(fmaxf(xm0.w, xc0.w), xp0.w) + xc0.w;
                r1.x = w * fmaxf(fmaxf(xm1.x, xc1.x), xp1.x) + xc1.x;
                r1.y = w * fmaxf(fmaxf(xm1.y, xc1.y), xp1.y) + xc1.y;
                r1.z = w * fmaxf(fmaxf(xm1.z, xc1.z), xp1.z) + xc1.z;
                r1.w = w * fmaxf(fmaxf(xm1.w, xc1.w), xp1.w) + xc1.w;
                o4[v0] = r0;
                o4[v1] = r1;
            }
        }
        return;
    }

    // ============================ conv path ============================
    // Last-arriving block does the whole branch alone (correctness only).
    __shared__ unsigned int s_last;
    if (tid == 0) {
        unsigned int prev = atomicAdd(&g_done, 1u);
        s_last = (prev == (unsigned)(ABLOCKS - 1)) ? 1u : 0u;
    }
    __syncthreads();
    if (!s_last) return;
    if (tid == 0) g_done = 0u;     // reset for next graph replay
    __syncthreads();

    bool is_nor = (idx <= 5);
    int k = is_nor ? (3 + 2 * (idx - 3)) : (3 + 2 * (idx - 6));

    if (is_nor) {
        // nor_conv: y[r,o] = sum_dk sum_i relu(x[r+dk-pad, i]) * W[o,i,dk]
        const float* W = (idx == 3) ? wn3 : ((idx == 4) ? wn5 : wn7);
        int pad = k >> 1;
        for (long e = tid; e < (long)M_ROWS * H; e += NTHREADS) {
            int o = (int)(e % H);
            int r = (int)(e / H);
            int b = r >> 9, s = r & 511;
            float acc = 0.f;
            for (int dk = 0; dk < k; dk++) {
                int s2 = s + dk - pad;
                if (s2 < 0 || s2 >= SLEN) continue;
                const float* xr = x + (long)((b << 9) + s2) * H;
                const float* wr = W + (long)o * H * k + dk;
                for (int i = 0; i < H; i++)
                    acc += fmaxf(xr[i], 0.f) * wr[(long)i * k];
            }
            g_y[e] = acc;
        }
    } else {
        // dil_conv: depthwise (dilation=2, pad=k-1) then pointwise
        const float* wd = (idx == 6) ? wd3 : ((idx == 7) ? wd5 : wd7);
        const float* wp = (idx == 6) ? wp3 : ((idx == 7) ? wp5 : wp7);
        for (long e = tid; e < (long)NELEM; e += NTHREADS) {
            int c = (int)(e % H);
            int r = (int)(e / H);
            int b = r >> 9, s = r & 511;
            float acc = 0.f;
            for (int dk = 0; dk < k; dk++) {
                int s2 = s + 2 * dk - (k - 1);
                if (s2 < 0 || s2 >= SLEN) continue;
                float xv = x[(long)((b << 9) + s2) * H + c];
                acc += wd[c * k + dk] * fmaxf(xv, 0.f);
            }
            g_y1[e] = acc;
        }
        __syncthreads();
        for (long e = tid; e < (long)M_ROWS * H; e += NTHREADS) {
            int o = (int)(e % H);
            int r = (int)(e / H);
            const float* yr = g_y1 + (long)r * H;
            const float* wr = wp + (long)o * H;
            float acc = 0.f;
            for (int i = 0; i < H; i++) acc += yr[i] * wr[i];
            g_y[e] = acc;
        }
    }
    __syncthreads();

    // BN stats (training mode) + normalize + residual
    {
        const float *ga, *be;
        switch (idx) {
            case 3: ga = gn3; be = bn3; break;
            case 4: ga = gn5; be = bn5; break;
            case 5: ga = gn7; be = bn7; break;
            case 6: ga = gd3; be = bd3; break;
            case 7: ga = gd5; be = bd5; break;
            default: ga = gd7; be = bd7; break;
        }
        const float invN = 1.f / (float)M_ROWS;
        for (int c = tid; c < H; c += NTHREADS) {
            float s = 0.f, q = 0.f;
            for (int r = 0; r < M_ROWS; r++) {
                float v = g_y[(long)r * H + c];
                s += v; q += v * v;
            }
            float mean = s * invN;
            float var  = q * invN - mean * mean;
            float inv  = rsqrtf(var + 1e-5f);
            float sc   = w * ga[c] * inv;
            g_scale[c] = sc;
            g_shift[c] = w * be[c] - mean * sc;
        }
        __syncthreads();
        for (long e = tid; e < (long)NELEM; e += NTHREADS) {
            int c = (int)(e % H);
            out[e] = g_scale[c] * g_y[e] + g_shift[c] + x[e];
        }
    }
}

// =====================================================================
extern "C" void kernel_launch(void* const* d_in, const int* in_sizes, int n_in,
                              void* d_out, int out_size) {
    const float* x     = (const float*)d_in[0];
    const float* u     = (const float*)d_in[1];
    const float* arch  = (const float*)d_in[2];
    fused_kernel<<<ABLOCKS, NTHREADS>>>(
        x, arch, u,
        (const float*)d_in[3],  (const float*)d_in[4],  (const float*)d_in[5],
        (const float*)d_in[6],  (const float*)d_in[7],  (const float*)d_in[8],
        (const float*)d_in[9],  (const float*)d_in[10], (const float*)d_in[11],
        (const float*)d_in[12], (const float*)d_in[13],
        (const float*)d_in[14], (const float*)d_in[15],
        (const float*)d_in[16], (const float*)d_in[17],
        (const float*)d_in[18], (const float*)d_in[19],
        (const float*)d_in[20], (const float*)d_in[21],
        (const float*)d_in[22], (const float*)d_in[23],
        (float*)d_out);
}

// round 12
// speedup vs baseline: 1.3544x; 1.3155x over previous
#include <cuda_runtime.h>
#include <math.h>

#define H 768
#define H4 (H/4)
#define SLEN 512
#define BATCH 8
#define M_ROWS (BATCH*SLEN)        // 4096
#define NELEM (BATCH*SLEN*H)       // 3145728
#define NVEC (NELEM/4)             // 786432

#define ABLOCKS 1024               // 1024*256*3 == NVEC exactly
#define NTHREADS 256
#define ELEMS 3
#define TSTRIDE (ABLOCKS*NTHREADS) // 262144

// ---- device globals (scratch; no allocation allowed) ----
__device__ float g_scale[H];
__device__ float g_shift[H];
__device__ float g_y[NELEM];          // conv output scratch [b,s,o]
__device__ float g_y1[NELEM];         // depthwise output scratch [b,s,c]
__device__ unsigned int g_done = 0;   // conv-path arrival counter (self-resetting)

// =====================================================================
// Minimal per-warp gumbel straight-through gate.
// logits = (log_softmax(a)+g)/TEM = (a+g)/TEM - const (shift-invariant)
//   t_i = (a_i + g_i)*0.1 ; idx = argmax t ; p_max = 1/sum exp(t - t_max)
// argmax via redux.max on a monotonic uint encoding (exact), lowest-index
// tie-break via ballot+ffs (matches jnp.argmax). Only 5 shuffles remain.
// =====================================================================
__device__ __forceinline__ void gate_warp_all(const float* __restrict__ arch,
                                              const float* __restrict__ u,
                                              int& r_idx, float& r_w) {
    const unsigned FULL = 0xffffffffu;
    int lane = threadIdx.x & 31;
    bool act = (lane < 10);
    float a  = act ? __ldg(arch + lane) : 0.f;
    float uu = act ? __ldg(u + lane) : 0.5f;
    float uc = fminf(fmaxf(uu, 1e-9f), 1.0f - 1e-9f);
    float g  = -__logf(-__logf(uc));
    float t  = act ? (a + g) * 0.1f : -1e30f;
    // monotonic float->uint encoding
    unsigned b   = __float_as_uint(t);
    unsigned key = b ^ ((unsigned)((int)b >> 31) | 0x80000000u);
    unsigned kmax = __reduce_max_sync(FULL, key);
    unsigned mask = __ballot_sync(FULL, key == kmax);
    int bi = __ffs(mask) - 1;
    // decode t_max arithmetically (no shuffle)
    unsigned m2 = (~(unsigned)((int)kmax >> 31)) | 0x80000000u;
    float tmax = __uint_as_float(kmax ^ m2);
    // p_max = 1 / sum exp(t - tmax); 5-level butterfly -> uniform in warp
    float p = act ? __expf(t - tmax) : 0.f;
    #pragma unroll
    for (int o = 16; o > 0; o >>= 1) p += __shfl_xor_sync(FULL, p, o);
    float bp = 1.0f / p;
    r_idx = bi;
    r_w   = (1.0f - bp) + bp;
}

// =====================================================================
// ONE kernel, ONE launch. Simple path: per-warp mini-gate overlapped
// with 3 prefetched float4 per thread. Conv path (correctness only):
// last block computes the whole branch alone with block-local syncs.
// =====================================================================
__global__ void __launch_bounds__(NTHREADS, 6)
fused_kernel(const float* __restrict__ x,
             const float* __restrict__ arch,
             const float* __restrict__ u,
             const float* __restrict__ wn3, const float* __restrict__ gn3, const float* __restrict__ bn3,
             const float* __restrict__ wn5, const float* __restrict__ gn5, const float* __restrict__ bn5,
             const float* __restrict__ wn7, const float* __restrict__ gn7, const float* __restrict__ bn7,
             const float* __restrict__ wd3, const float* __restrict__ wp3,
             const float* __restrict__ gd3, const float* __restrict__ bd3,
             const float* __restrict__ wd5, const float* __restrict__ wp5,
             const float* __restrict__ gd5, const float* __restrict__ bd5,
             const float* __restrict__ wd7, const float* __restrict__ wp7,
             const float* __restrict__ gd7, const float* __restrict__ bd7,
             float* __restrict__ out) {
    int tid = threadIdx.x;
    const float4* x4 = (const float4*)x;
    float4* o4 = (float4*)out;
    int v0 = blockIdx.x * NTHREADS + tid;

    // Gate loads head the longest dependency chain: issue them FIRST.
    int lane = tid & 31;
    bool act = (lane < 10);
    float ga_a  = act ? __ldg(arch + lane) : 0.f;
    float ga_u  = act ? __ldg(u + lane) : 0.5f;

    // Prefetch center elements (branch-independent).
    float4 xc[ELEMS];
    #pragma unroll
    for (int j = 0; j < ELEMS; j++) xc[j] = x4[v0 + j * TSTRIDE];

    // ---- gate compute (loads already in flight) ----
    const unsigned FULL = 0xffffffffu;
    float uc = fminf(fmaxf(ga_u, 1e-9f), 1.0f - 1e-9f);
    float gg = -__logf(-__logf(uc));
    float t  = act ? (ga_a + gg) * 0.1f : -1e30f;
    unsigned bbits = __float_as_uint(t);
    unsigned key   = bbits ^ ((unsigned)((int)bbits >> 31) | 0x80000000u);
    unsigned kmax  = __reduce_max_sync(FULL, key);
    unsigned mask  = __ballot_sync(FULL, key == kmax);
    int idx = __ffs(mask) - 1;
    unsigned m2 = (~(unsigned)((int)kmax >> 31)) | 0x80000000u;
    float tmax = __uint_as_float(kmax ^ m2);
    float p = act ? __expf(t - tmax) : 0.f;
    #pragma unroll
    for (int o = 16; o > 0; o >>= 1) p += __shfl_xor_sync(FULL, p, o);
    float bp = 1.0f / p;
    float w = (1.0f - bp) + bp;

    // =========================== simple path ===========================
    if (idx < 3 || idx > 8) {
        if (idx == 0) {                          // none: out = x (bit-exact)
            #pragma unroll
            for (int j = 0; j < ELEMS; j++) o4[v0 + j * TSTRIDE] = xc[j];
        } else if (idx == 9) {                   // skip: out = (1+w)*x
            float wp1 = 1.0f + w;
            #pragma unroll
            for (int j = 0; j < ELEMS; j++) {
                float4 r;
                r.x = wp1 * xc[j].x; r.y = wp1 * xc[j].y;
                r.z = wp1 * xc[j].z; r.w = wp1 * xc[j].w;
                o4[v0 + j * TSTRIDE] = r;
            }
        } else if (idx == 1) {                   // avg pool3 (pad counts as 0)
            float4 z = make_float4(0.f, 0.f, 0.f, 0.f);
            float4 xm[ELEMS], xp[ELEMS];
            #pragma unroll
            for (int j = 0; j < ELEMS; j++) {
                int v = v0 + j * TSTRIDE;
                int s = (v / H4) & (SLEN - 1);
                xm[j] = (s > 0)        ? x4[v - H4] : z;
                xp[j] = (s < SLEN - 1) ? x4[v + H4] : z;
            }
            float w3 = w * (1.f / 3.f);
            #pragma unroll
            for (int j = 0; j < ELEMS; j++) {
                float4 r;
                r.x = w3 * (xm[j].x + xc[j].x + xp[j].x) + xc[j].x;
                r.y = w3 * (xm[j].y + xc[j].y + xp[j].y) + xc[j].y;
                r.z = w3 * (xm[j].z + xc[j].z + xp[j].z) + xc[j].z;
                r.w = w3 * (xm[j].w + xc[j].w + xp[j].w) + xc[j].w;
                o4[v0 + j * TSTRIDE] = r;
            }
        } else {                                 // max pool3 (-inf pad)
            const float NINF = -__int_as_float(0x7f800000);
            float4 ni = make_float4(NINF, NINF, NINF, NINF);
            float4 xm[ELEMS], xp[ELEMS];
            #pragma unroll
            for (int j = 0; j < ELEMS; j++) {
                int v = v0 + j * TSTRIDE;
                int s = (v / H4) & (SLEN - 1);
                xm[j] = (s > 0)        ? x4[v - H4] : ni;
                xp[j] = (s < SLEN - 1) ? x4[v + H4] : ni;
            }
            #pragma unroll
            for (int j = 0; j < ELEMS; j++) {
                float4 r;
                r.x = w * fmaxf(fmaxf(xm[j].x, xc[j].x), xp[j].x) + xc[j].x;
                r.y = w * fmaxf(fmaxf(xm[j].y, xc[j].y), xp[j].y) + xc[j].y;
                r.z = w * fmaxf(fmaxf(xm[j].z, xc[j].z), xp[j].z) + xc[j].z;
                r.w = w * fmaxf(fmaxf(xm[j].w, xc[j].w), xp[j].w) + xc[j].w;
                o4[v0 + j * TSTRIDE] = r;
            }
        }
        return;
    }

    // ============================ conv path ============================
    // Last-arriving block does the whole branch alone (correctness only).
    __shared__ unsigned int s_last;
    if (tid == 0) {
        unsigned int prev = atomicAdd(&g_done, 1u);
        s_last = (prev == (unsigned)(ABLOCKS - 1)) ? 1u : 0u;
    }
    __syncthreads();
    if (!s_last) return;
    if (tid == 0) g_done = 0u;     // reset for next graph replay
    __syncthreads();

    bool is_nor = (idx <= 5);
    int k = is_nor ? (3 + 2 * (idx - 3)) : (3 + 2 * (idx - 6));

    if (is_nor) {
        // nor_conv: y[r,o] = sum_dk sum_i relu(x[r+dk-pad, i]) * W[o,i,dk]
        const float* W = (idx == 3) ? wn3 : ((idx == 4) ? wn5 : wn7);
        int pad = k >> 1;
        for (long e = tid; e < (long)M_ROWS * H; e += NTHREADS) {
            int o = (int)(e % H);
            int r = (int)(e / H);
            int b = r >> 9, s = r & 511;
            float acc = 0.f;
            for (int dk = 0; dk < k; dk++) {
                int s2 = s + dk - pad;
                if (s2 < 0 || s2 >= SLEN) continue;
                const float* xr = x + (long)((b << 9) + s2) * H;
                const float* wr = W + (long)o * H * k + dk;
                for (int i = 0; i < H; i++)
                    acc += fmaxf(xr[i], 0.f) * wr[(long)i * k];
            }
            g_y[e] = acc;
        }
    } else {
        // dil_conv: depthwise (dilation=2, pad=k-1) then pointwise
        const float* wd = (idx == 6) ? wd3 : ((idx == 7) ? wd5 : wd7);
        const float* wp = (idx == 6) ? wp3 : ((idx == 7) ? wp5 : wp7);
        for (long e = tid; e < (long)NELEM; e += NTHREADS) {
            int c = (int)(e % H);
            int r = (int)(e / H);
            int b = r >> 9, s = r & 511;
            float acc = 0.f;
            for (int dk = 0; dk < k; dk++) {
                int s2 = s + 2 * dk - (k - 1);
                if (s2 < 0 || s2 >= SLEN) continue;
                float xv = x[(long)((b << 9) + s2) * H + c];
                acc += wd[c * k + dk] * fmaxf(xv, 0.f);
            }
            g_y1[e] = acc;
        }
        __syncthreads();
        for (long e = tid; e < (long)M_ROWS * H; e += NTHREADS) {
            int o = (int)(e % H);
            int r = (int)(e / H);
            const float* yr = g_y1 + (long)r * H;
            const float* wr = wp + (long)o * H;
            float acc = 0.f;
            for (int i = 0; i < H; i++) acc += yr[i] * wr[i];
            g_y[e] = acc;
        }
    }
    __syncthreads();

    // BN stats (training mode) + normalize + residual
    {
        const float *gaP, *beP;
        switch (idx) {
            case 3: gaP = gn3; beP = bn3; break;
            case 4: gaP = gn5; beP = bn5; break;
            case 5: gaP = gn7; beP = bn7; break;
            case 6: gaP = gd3; beP = bd3; break;
            case 7: gaP = gd5; beP = bd5; break;
            default: gaP = gd7; beP = bd7; break;
        }
        const float invN = 1.f / (float)M_ROWS;
        for (int c = tid; c < H; c += NTHREADS) {
            float s = 0.f, q = 0.f;
            for (int r = 0; r < M_ROWS; r++) {
                float v = g_y[(long)r * H + c];
                s += v; q += v * v;
            }
            float mean = s * invN;
            float var  = q * invN - mean * mean;
            float inv  = rsqrtf(var + 1e-5f);
            float sc   = w * gaP[c] * inv;
            g_scale[c] = sc;
            g_shift[c] = w * beP[c] - mean * sc;
        }
        __syncthreads();
        for (long e = tid; e < (long)NELEM; e += NTHREADS) {
            int c = (int)(e % H);
            out[e] = g_scale[c] * g_y[e] + g_shift[c] + x[e];
        }
    }
}

// =====================================================================
extern "C" void kernel_launch(void* const* d_in, const int* in_sizes, int n_in,
                              void* d_out, int out_size) {
    const float* x     = (const float*)d_in[0];
    const float* u     = (const float*)d_in[1];
    const float* arch  = (const float*)d_in[2];
    fused_kernel<<<ABLOCKS, NTHREADS>>>(
        x, arch, u,
        (const float*)d_in[3],  (const float*)d_in[4],  (const float*)d_in[5],
        (const float*)d_in[6],  (const float*)d_in[7],  (const float*)d_in[8],
        (const float*)d_in[9],  (const float*)d_in[10], (const float*)d_in[11],
        (const float*)d_in[12], (const float*)d_in[13],
        (const float*)d_in[14], (const float*)d_in[15],
        (const float*)d_in[16], (const float*)d_in[17],
        (const float*)d_in[18], (const float*)d_in[19],
        (const float*)d_in[20], (const float*)d_in[21],
        (const float*)d_in[22], (const float*)d_in[23],
        (float*)d_out);
}